// round 15
// baseline (speedup 1.0000x reference)
#include <cuda_runtime.h>
#include <cuda_fp16.h>
#include <cstdint>
#include <cstddef>

#define NT 256
#define XP 72   // halves per smem matrix row (144B: conflict-free ldmatrix)

namespace {
constexpr int Bb = 2, Ss = 512, Ll = 384, CMc = 64;
constexpr int Sh = 256;   // rows per CTA (cluster of 2 covers S=512)

struct __align__(16) SMem {
    __half x[Sh * XP];       // post-LN x fp16 (local rows), later t     36,864B
    __half wvB[64 * XP];     // wv^T tile                                  9,216B
    union {
        float LG[8 * Sh];    // logits->attn [h][s_loc]                    8,192B
        struct { __half wgB[64 * XP]; __half woB[64 * XP]; } go;   //    18,432B
    } u;
    float maskS[Sh];
    float pbuf[8 * 64];      // qin partials; og partials
    __half a_h[8 * XP];      // a fp16 [h][j]
    float qin[64];
    float qinP[64];          // peer qin mailbox
    float og[64];
    float ogPm[64];          // peer og mailbox
    float bgS[64];
    float qsm[64];
    float red[8];
    float hmsP[16];          // peer (max, sumexp) mailbox per head
    float mloc, msP;
};
}  // namespace

__device__ __forceinline__ uint32_t s2u(const void* p) {
    uint32_t a;
    asm("{ .reg .u64 t; cvta.to.shared.u64 t, %1; cvt.u32.u64 %0, t; }" : "=r"(a) : "l"(p));
    return a;
}
__device__ __forceinline__ void ldmA(uint32_t* a, uint32_t addr) {
    asm volatile("ldmatrix.sync.aligned.m8n8.x4.shared.b16 {%0,%1,%2,%3}, [%4];"
                 : "=r"(a[0]), "=r"(a[1]), "=r"(a[2]), "=r"(a[3]) : "r"(addr));
}
__device__ __forceinline__ void mma16816(float* d, const uint32_t* a, const uint32_t* b) {
    asm volatile(
        "mma.sync.aligned.m16n8k16.row.col.f32.f16.f16.f32 "
        "{%0,%1,%2,%3}, {%4,%5,%6,%7}, {%8,%9}, {%0,%1,%2,%3};"
        : "+f"(d[0]), "+f"(d[1]), "+f"(d[2]), "+f"(d[3])
        : "r"(a[0]), "r"(a[1]), "r"(a[2]), "r"(a[3]), "r"(b[0]), "r"(b[1]));
}
__device__ __forceinline__ float sgm(float x) { return 1.0f / (1.0f + __expf(-x)); }
__device__ __forceinline__ uint32_t packh2(float a, float b) {
    __half2 h = __floats2half2_rn(a, b);
    return *reinterpret_cast<uint32_t*>(&h);
}
__device__ __forceinline__ void st_peer(uint32_t laddr, uint32_t peer, float v) {
    uint32_t ra;
    asm volatile("mapa.shared::cluster.u32 %0, %1, %2;" : "=r"(ra) : "r"(laddr), "r"(peer));
    asm volatile("st.shared::cluster.f32 [%0], %1;" :: "r"(ra), "f"(v) : "memory");
}
__device__ __forceinline__ void cluster_sync() {
    asm volatile("barrier.cluster.arrive.aligned;" ::: "memory");
    asm volatile("barrier.cluster.wait.aligned;" ::: "memory");
}
__device__ __forceinline__ uint32_t ctarank() {
    uint32_t r;
    asm("mov.u32 %0, %%cluster_ctarank;" : "=r"(r));
    return r;
}

__global__ void __launch_bounds__(NT, 3) __cluster_dims__(2, 1, 1)
msa_col_global_attn(const float* __restrict__ m, const float* __restrict__ msa_mask,
                    const float* __restrict__ lnw, const float* __restrict__ lnb,
                    const float* __restrict__ wq, const float* __restrict__ wk,
                    const float* __restrict__ wv, const float* __restrict__ wg,
                    const float* __restrict__ bg, const float* __restrict__ wo,
                    const float* __restrict__ bo, float* __restrict__ out)
{
    extern __shared__ __align__(16) char smraw[];
    SMem& sm = *reinterpret_cast<SMem*>(smraw);
    const int tid = threadIdx.x;
    const int w = tid >> 5, lane = tid & 31;
    const uint32_t rank = ctarank();
    const uint32_t peer = rank ^ 1u;
    const int col = blockIdx.x >> 1;
    const int b = col / Ll, l = col - b * Ll;
    const int sBase = (int)rank * Sh;
    const size_t rowStride = (size_t)Ll * CMc;
    const float* mBase = m + ((size_t)b * Ss * Ll + l) * CMc;
    float* oBase = out + ((size_t)b * Ss * Ll + l) * CMc;

    // ---- Phase 0: mask, wv tile, bg, LayerNorm (warp owns 32 local rows) + qin fold ----
    float mk = msa_mask[((size_t)b * Ss + sBase + tid) * Ll + l];
    sm.maskS[tid] = mk;
    {
        float ms = mk;
#pragma unroll
        for (int o = 16; o; o >>= 1) ms += __shfl_xor_sync(0xffffffffu, ms, o);
        if (lane == 0) sm.red[w] = ms;
    }
    for (int idx = tid; idx < 4096; idx += NT) {
        int n = idx & 63, k = idx >> 6;
        sm.wvB[n * XP + k] = __float2half(__ldg(&wv[k * 64 + n]));
    }
    if (tid < 64) sm.bgS[tid] = __ldg(&bg[tid]);
    {
        const float lwA = lnw[lane], lwB = lnw[lane + 32];
        const float lbA = lnb[lane], lbB = lnb[lane + 32];
        float qA = 0.f, qB = 0.f;
#pragma unroll 1
        for (int rb = 0; rb < 4; rb++) {
            float a0[8], a1[8];
#pragma unroll
            for (int r = 0; r < 8; r++) {
                int s = w * 32 + rb * 8 + r;
                const float* mp = mBase + (size_t)(sBase + s) * rowStride;
                a0[r] = mp[lane];
                a1[r] = mp[lane + 32];
            }
#pragma unroll
            for (int r = 0; r < 8; r++) {
                int s = w * 32 + rb * 8 + r;
                float su = a0[r] + a1[r];
                float sq = fmaf(a0[r], a0[r], a1[r] * a1[r]);
#pragma unroll
                for (int o = 16; o; o >>= 1) {
                    su += __shfl_xor_sync(0xffffffffu, su, o);
                    sq += __shfl_xor_sync(0xffffffffu, sq, o);
                }
                float mu = su * (1.0f / 64.0f);
                float var = sq * (1.0f / 64.0f) - mu * mu;
                float rs = rsqrtf(var + 1e-5f);
                float vA = (a0[r] - mu) * rs * lwA + lbA;
                float vB = (a1[r] - mu) * rs * lwB + lbB;
                sm.x[s * XP + lane]      = __float2half(vA);
                sm.x[s * XP + lane + 32] = __float2half(vB);
                float mks = __shfl_sync(0xffffffffu, mk, rb * 8 + r);
                qA = fmaf(vA, mks, qA);
                qB = fmaf(vB, mks, qB);
            }
        }
        sm.pbuf[w * 64 + lane]      = qA;
        sm.pbuf[w * 64 + lane + 32] = qB;
    }
    __syncthreads();  // S1

    // ---- qin local sum + exchange ----
    if (tid < 64) {
        float acc = 0.f;
#pragma unroll
        for (int i = 0; i < 8; i++) acc += sm.pbuf[i * 64 + tid];
        sm.qin[tid] = acc;
        st_peer(s2u(&sm.qinP[tid]), peer, acc);
    }
    if (tid == 0) {
        float d = 0.f;
#pragma unroll
        for (int i = 0; i < 8; i++) d += sm.red[i];
        sm.mloc = d;
        st_peer(s2u(&sm.msP), peer, d);
    }
    cluster_sync();  // sync A (also orders smem like __syncthreads)

    // ---- warp-0 chain: combined qin -> q -> a_h (fp16 [h][j]) ----
    if (w == 0) {
        float inv = 1.0f / fmaxf(sm.mloc + sm.msP, 1.0f);
        float q0 = (sm.qin[lane] + sm.qinP[lane]) * inv;
        float q1 = (sm.qin[lane + 32] + sm.qinP[lane + 32]) * inv;
        sm.qin[lane] = q0;
        sm.qin[lane + 32] = q1;
        __syncwarp();
        float a0 = 0.f, a1 = 0.f;
#pragma unroll
        for (int j = 0; j < 64; j++) {
            float qj = sm.qin[j];
            a0 = fmaf(qj, __ldg(&wq[j * 64 + lane]), a0);
            a1 = fmaf(qj, __ldg(&wq[j * 64 + lane + 32]), a1);
        }
        sm.qsm[lane] = a0;
        sm.qsm[lane + 32] = a1;
        __syncwarp();
#pragma unroll 1
        for (int t = 0; t < 16; t++) {
            int idx = t * 32 + lane;
            int j = idx >> 3, h = idx & 7;
            float acc = 0.f;
#pragma unroll
            for (int c = 0; c < 8; c++)
                acc = fmaf(sm.qsm[h * 8 + c], __ldg(&wk[j * 64 + h * 8 + c]), acc);
            sm.a_h[h * XP + j] = __float2half(acc * 0.35355339059327373f);  // 1/sqrt(C)
        }
    }
    __syncthreads();  // S2

    // ---- Logits via HMMA: warp w local rows w*32..+31 ----
    {
        uint32_t Bf[4][2];
#pragma unroll
        for (int kt = 0; kt < 4; kt++) {
            int row = lane >> 2;
            int c2 = kt * 16 + (lane & 3) * 2;
            Bf[kt][0] = *reinterpret_cast<const uint32_t*>(&sm.a_h[row * XP + c2]);
            Bf[kt][1] = *reinterpret_cast<const uint32_t*>(&sm.a_h[row * XP + c2 + 8]);
        }
#pragma unroll
        for (int mt = 0; mt < 2; mt++) {
            int s0 = w * 32 + mt * 16;
            uint32_t A[4][4];
#pragma unroll
            for (int kt = 0; kt < 4; kt++)
                ldmA(A[kt], s2u(&sm.x[(s0 + (lane & 15)) * XP + kt * 16 + ((lane >> 4) << 3)]));
            float acc[4] = {0, 0, 0, 0};
#pragma unroll
            for (int kt = 0; kt < 4; kt++) mma16816(acc, A[kt], Bf[kt]);
            int r = s0 + (lane >> 2);
            int h0 = (lane & 3) * 2;
            float mA = sm.maskS[r], mB = sm.maskS[r + 8];
            sm.u.LG[h0 * Sh + r]           = (mA != 0.0f) ? acc[0] : -1e9f;
            sm.u.LG[(h0 + 1) * Sh + r]     = (mA != 0.0f) ? acc[1] : -1e9f;
            sm.u.LG[h0 * Sh + r + 8]       = (mB != 0.0f) ? acc[2] : -1e9f;
            sm.u.LG[(h0 + 1) * Sh + r + 8] = (mB != 0.0f) ? acc[3] : -1e9f;
        }
    }
    __syncthreads();  // S3

    // ---- split softmax: local max/sumexp, exchange, scale ----
    {
        float vals[8];
        float lm = -3.4e38f;
#pragma unroll
        for (int k = 0; k < 8; k++) {
            vals[k] = sm.u.LG[w * Sh + lane + k * 32];
            lm = fmaxf(lm, vals[k]);
        }
#pragma unroll
        for (int o = 16; o; o >>= 1) lm = fmaxf(lm, __shfl_xor_sync(0xffffffffu, lm, o));
        float ls = 0.f;
#pragma unroll
        for (int k = 0; k < 8; k++) {
            vals[k] = __expf(vals[k] - lm);
            ls += vals[k];
        }
#pragma unroll
        for (int o = 16; o; o >>= 1) ls += __shfl_xor_sync(0xffffffffu, ls, o);
        if (lane == 0) {
            st_peer(s2u(&sm.hmsP[w]), peer, lm);
            st_peer(s2u(&sm.hmsP[8 + w]), peer, ls);
        }
        cluster_sync();  // sync B
        float fH;
        if (lane == 0) {
            float mP = sm.hmsP[w], sP = sm.hmsP[8 + w];
            float M = fmaxf(lm, mP);
            float D = ls * __expf(lm - M) + sP * __expf(mP - M);
            fH = __expf(lm - M) / D;
        }
        fH = __shfl_sync(0xffffffffu, fH, 0);
#pragma unroll
        for (int k = 0; k < 8; k++) sm.u.LG[w * Sh + lane + k * 32] = vals[k] * fH;
    }
    __syncthreads();  // S4: local attn (globally normalized) ready

    // ---- Fused Pass V + og partial: warp w local rows w*32..+31, all 64 cols ----
    {
        float ogp[16];
#pragma unroll
        for (int k = 0; k < 16; k++) ogp[k] = 0.f;
        const int k0 = (lane & 3) * 2;
#pragma unroll 1
        for (int mt = 0; mt < 2; mt++) {
            int s0 = w * 32 + mt * 16;
            uint32_t A[4][4];
#pragma unroll
            for (int kt = 0; kt < 4; kt++)
                ldmA(A[kt], s2u(&sm.x[(s0 + (lane & 15)) * XP + kt * 16 + ((lane >> 4) << 3)]));
            int r = s0 + (lane >> 2);
#pragma unroll
            for (int nt = 0; nt < 8; nt++) {
                uint32_t Bv[4][2];
#pragma unroll
                for (int kt = 0; kt < 4; kt++) {
                    int row = nt * 8 + (lane >> 2);
                    int c2 = kt * 16 + k0;
                    Bv[kt][0] = *reinterpret_cast<const uint32_t*>(&sm.wvB[row * XP + c2]);
                    Bv[kt][1] = *reinterpret_cast<const uint32_t*>(&sm.wvB[row * XP + c2 + 8]);
                }
                float acc[4] = {0, 0, 0, 0};
#pragma unroll
                for (int kt = 0; kt < 4; kt++) mma16816(acc, A[kt], Bv[kt]);
                float aA = sm.u.LG[nt * Sh + r];
                float aB = sm.u.LG[nt * Sh + r + 8];
                ogp[2 * nt]     = fmaf(aA, acc[0], fmaf(aB, acc[2], ogp[2 * nt]));
                ogp[2 * nt + 1] = fmaf(aA, acc[1], fmaf(aB, acc[3], ogp[2 * nt + 1]));
            }
        }
#pragma unroll
        for (int k = 0; k < 16; k++) {
            ogp[k] += __shfl_xor_sync(0xffffffffu, ogp[k], 4);
            ogp[k] += __shfl_xor_sync(0xffffffffu, ogp[k], 8);
            ogp[k] += __shfl_xor_sync(0xffffffffu, ogp[k], 16);
        }
        if (lane < 4) {
#pragma unroll
            for (int nt = 0; nt < 8; nt++) {
                sm.pbuf[w * 64 + nt * 8 + k0]     = ogp[2 * nt];
                sm.pbuf[w * 64 + nt * 8 + k0 + 1] = ogp[2 * nt + 1];
            }
        }
    }
    __syncthreads();  // S5: LG dead; og partials ready

    // ---- og local sum + exchange; stage wg/wo tiles into union ----
    if (tid < 64) {
        float acc = 0.f;
#pragma unroll
        for (int w2 = 0; w2 < 8; w2++) acc += sm.pbuf[w2 * 64 + tid];
        sm.og[tid] = acc;
        st_peer(s2u(&sm.ogPm[tid]), peer, acc);
    }
    for (int idx = tid; idx < 4096; idx += NT) {
        int n = idx & 63, k = idx >> 6;
        sm.u.go.wgB[n * XP + k] = __float2half(__ldg(&wg[k * 64 + n]));
        sm.u.go.woB[n * XP + k] = __float2half(__ldg(&wo[k * 64 + n]));
    }
    cluster_sync();  // sync C
    if (tid < 64) sm.og[tid] += sm.ogPm[tid];
    __syncthreads();  // S6: og + wg/wo tiles ready

    // ---- Fused G+O: warp w local rows w*32..+31; t staged through x smem ----
    {
        const int k0 = (lane & 3) * 2;
#pragma unroll 1
        for (int mt2 = 0; mt2 < 2; mt2++) {
            int s0 = w * 32 + mt2 * 16;
            uint32_t Ax[4][4];
#pragma unroll
            for (int kt = 0; kt < 4; kt++)
                ldmA(Ax[kt], s2u(&sm.x[(s0 + (lane & 15)) * XP + kt * 16 + ((lane >> 4) << 3)]));
            int r = s0 + (lane >> 2);
            // GEMM1 + epilogue: t overwrites x rows s0..s0+15 (dead for this warp)
#pragma unroll
            for (int nt = 0; nt < 8; nt++) {
                uint32_t Bg[4][2];
#pragma unroll
                for (int kt = 0; kt < 4; kt++) {
                    int row = nt * 8 + (lane >> 2);
                    int c2 = kt * 16 + k0;
                    Bg[kt][0] = *reinterpret_cast<const uint32_t*>(&sm.u.go.wgB[row * XP + c2]);
                    Bg[kt][1] = *reinterpret_cast<const uint32_t*>(&sm.u.go.wgB[row * XP + c2 + 8]);
                }
                float acc[4] = {0, 0, 0, 0};
#pragma unroll
                for (int kt = 0; kt < 4; kt++) mma16816(acc, Ax[kt], Bg[kt]);
                int c = nt * 8 + k0;
                float ogv0 = sm.og[c], ogv1 = sm.og[c + 1];
                float bg0 = sm.bgS[c], bg1 = sm.bgS[c + 1];
                *reinterpret_cast<uint32_t*>(&sm.x[r * XP + c]) =
                    packh2(ogv0 * sgm(acc[0] + bg0), ogv1 * sgm(acc[1] + bg1));
                *reinterpret_cast<uint32_t*>(&sm.x[(r + 8) * XP + c]) =
                    packh2(ogv0 * sgm(acc[2] + bg0), ogv1 * sgm(acc[3] + bg1));
            }
            __syncwarp();
            uint32_t Ap[4][4];
#pragma unroll
            for (int kt = 0; kt < 4; kt++)
                ldmA(Ap[kt], s2u(&sm.x[(s0 + (lane & 15)) * XP + kt * 16 + ((lane >> 4) << 3)]));
            // GEMM2: out = (t @ wo + bo) * mask -> global
            float mA = sm.maskS[r], mB = sm.maskS[r + 8];
#pragma unroll
            for (int nt2 = 0; nt2 < 8; nt2++) {
                uint32_t Bo[4][2];
#pragma unroll
                for (int kt = 0; kt < 4; kt++) {
                    int row = nt2 * 8 + (lane >> 2);
                    int c2 = kt * 16 + k0;
                    Bo[kt][0] = *reinterpret_cast<const uint32_t*>(&sm.u.go.woB[row * XP + c2]);
                    Bo[kt][1] = *reinterpret_cast<const uint32_t*>(&sm.u.go.woB[row * XP + c2 + 8]);
                }
                float acc2[4] = {0, 0, 0, 0};
#pragma unroll
                for (int kt = 0; kt < 4; kt++) mma16816(acc2, Ap[kt], Bo[kt]);
                int c = nt2 * 8 + k0;
                float bo0 = __ldg(&bo[c]), bo1 = __ldg(&bo[c + 1]);
                *reinterpret_cast<float2*>(oBase + (size_t)(sBase + r) * rowStride + c) =
                    make_float2((acc2[0] + bo0) * mA, (acc2[1] + bo1) * mA);
                *reinterpret_cast<float2*>(oBase + (size_t)(sBase + r + 8) * rowStride + c) =
                    make_float2((acc2[2] + bo0) * mB, (acc2[3] + bo1) * mB);
            }
        }
    }
}

extern "C" void kernel_launch(void* const* d_in, const int* in_sizes, int n_in,
                              void* d_out, int out_size)
{
    (void)in_sizes; (void)n_in; (void)out_size;
    const float* m    = (const float*)d_in[0];
    const float* mask = (const float*)d_in[1];
    const float* lnw  = (const float*)d_in[2];
    const float* lnb  = (const float*)d_in[3];
    const float* wq   = (const float*)d_in[4];
    const float* wk   = (const float*)d_in[5];
    const float* wv   = (const float*)d_in[6];
    const float* wg   = (const float*)d_in[7];
    const float* bg   = (const float*)d_in[8];
    const float* wo   = (const float*)d_in[9];
    const float* bo   = (const float*)d_in[10];
    float* out = (float*)d_out;

    cudaFuncSetAttribute(msa_col_global_attn,
                         cudaFuncAttributeMaxDynamicSharedMemorySize,
                         (int)sizeof(SMem));
    msa_col_global_attn<<<Bb * Ll * 2, NT, sizeof(SMem)>>>(
        m, mask, lnw, lnb, wq, wk, wv, wg, bg, wo, bo, out);
}

// round 16
// speedup vs baseline: 1.1290x; 1.1290x over previous
#include <cuda_runtime.h>
#include <cuda_fp16.h>
#include <cstdint>
#include <cstddef>

#define NT 256
#define XP 72   // halves per smem matrix row (144B: conflict-free ldmatrix, 16B-aligned)

namespace {
constexpr int Bb = 2, Ss = 512, Ll = 384, CMc = 64;

struct __align__(16) SMem {
    __half x[512 * XP];      // post-LN x fp16, row-major [s][c]     73,728B
    __half wvB[64 * XP];     // wv^T tile: row n, col k               9,216B
    union {
        float LG[8 * 512];   // logits->attn [h][s]                  16,384B
        struct { __half wgB[64 * XP]; __half woB[64 * XP]; } go;  // 18,432B
    } u;
    float maskS[512];
    float pbuf[8 * 64];      // qin partials; og partials
    __half a_h[8 * XP];      // a fp16 [h][j]
    float qin[64];
    float qsm[64];
    float og[64];
    float bgS[64];
    float red[8];
};
}  // namespace

__device__ __forceinline__ uint32_t s2u(const void* p) {
    uint32_t a;
    asm("{ .reg .u64 t; cvta.to.shared.u64 t, %1; cvt.u32.u64 %0, t; }" : "=r"(a) : "l"(p));
    return a;
}
__device__ __forceinline__ void ldmA(uint32_t* a, uint32_t addr) {
    asm volatile("ldmatrix.sync.aligned.m8n8.x4.shared.b16 {%0,%1,%2,%3}, [%4];"
                 : "=r"(a[0]), "=r"(a[1]), "=r"(a[2]), "=r"(a[3]) : "r"(addr));
}
__device__ __forceinline__ void mma16816(float* d, const uint32_t* a, const uint32_t* b) {
    asm volatile(
        "mma.sync.aligned.m16n8k16.row.col.f32.f16.f16.f32 "
        "{%0,%1,%2,%3}, {%4,%5,%6,%7}, {%8,%9}, {%0,%1,%2,%3};"
        : "+f"(d[0]), "+f"(d[1]), "+f"(d[2]), "+f"(d[3])
        : "r"(a[0]), "r"(a[1]), "r"(a[2]), "r"(a[3]), "r"(b[0]), "r"(b[1]));
}
__device__ __forceinline__ float sgm(float x) { return 1.0f / (1.0f + __expf(-x)); }
__device__ __forceinline__ uint32_t packh2(float a, float b) {
    __half2 h = __floats2half2_rn(a, b);
    return *reinterpret_cast<uint32_t*>(&h);
}

__global__ void __launch_bounds__(NT, 2)
msa_col_global_attn(const float* __restrict__ m, const float* __restrict__ msa_mask,
                    const float* __restrict__ lnw, const float* __restrict__ lnb,
                    const float* __restrict__ wq, const float* __restrict__ wk,
                    const float* __restrict__ wv, const float* __restrict__ wg,
                    const float* __restrict__ bg, const float* __restrict__ wo,
                    const float* __restrict__ bo, float* __restrict__ out)
{
    extern __shared__ __align__(16) char smraw[];
    SMem& sm = *reinterpret_cast<SMem*>(smraw);
    const int tid = threadIdx.x;
    const int w = tid >> 5, lane = tid & 31;
    const int b = blockIdx.x / Ll, l = blockIdx.x - b * Ll;
    const size_t rowStride = (size_t)Ll * CMc;
    const float* mBase = m + ((size_t)b * Ss * Ll + l) * CMc;
    float* oBase = out + ((size_t)b * Ss * Ll + l) * CMc;
    // ldmatrix.x4 B-operand addressing helpers (lane-dependent, loop-invariant)
    const int bRowSel = lane & 7;          // row within 8-row n-block
    const int bKSel = (lane >> 3) << 3;    // which 8-col k-piece this lane fetches

    // ---- Phase 0: mask, wv tile, bg, LayerNorm (warp owns 64 rows) + qin fold ----
    const int row0 = w * 64 + lane, row1 = row0 + 32;
    float mkA = msa_mask[((size_t)b * Ss + row0) * Ll + l];
    float mkB = msa_mask[((size_t)b * Ss + row1) * Ll + l];
    sm.maskS[row0] = mkA;
    sm.maskS[row1] = mkB;
    {
        float ms = mkA + mkB;
#pragma unroll
        for (int o = 16; o; o >>= 1) ms += __shfl_xor_sync(0xffffffffu, ms, o);
        if (lane == 0) sm.red[w] = ms;
    }
    for (int idx = tid; idx < 4096; idx += NT) {
        int n = idx & 63, k = idx >> 6;
        sm.wvB[n * XP + k] = __float2half(__ldg(&wv[k * 64 + n]));
    }
    if (tid < 64) sm.bgS[tid] = __ldg(&bg[tid]);
    {
        const float lwA = lnw[lane], lwB = lnw[lane + 32];
        const float lbA = lnb[lane], lbB = lnb[lane + 32];
        float qA = 0.f, qB = 0.f;
#pragma unroll 1
        for (int rb = 0; rb < 8; rb++) {
            float a0[8], a1[8];
#pragma unroll
            for (int r = 0; r < 8; r++) {
                int s = w * 64 + rb * 8 + r;
                const float* mp = mBase + (size_t)s * rowStride;
                a0[r] = mp[lane];
                a1[r] = mp[lane + 32];
            }
            float msel = (rb < 4) ? mkA : mkB;
            int bidx = (rb < 4) ? rb * 8 : rb * 8 - 32;
#pragma unroll
            for (int r = 0; r < 8; r++) {
                int s = w * 64 + rb * 8 + r;
                float su = a0[r] + a1[r];
                float sq = fmaf(a0[r], a0[r], a1[r] * a1[r]);
#pragma unroll
                for (int o = 16; o; o >>= 1) {
                    su += __shfl_xor_sync(0xffffffffu, su, o);
                    sq += __shfl_xor_sync(0xffffffffu, sq, o);
                }
                float mu = su * (1.0f / 64.0f);
                float var = sq * (1.0f / 64.0f) - mu * mu;
                float rs = rsqrtf(var + 1e-5f);
                float vA = (a0[r] - mu) * rs * lwA + lbA;
                float vB = (a1[r] - mu) * rs * lwB + lbB;
                sm.x[s * XP + lane]      = __float2half(vA);
                sm.x[s * XP + lane + 32] = __float2half(vB);
                float mks = __shfl_sync(0xffffffffu, msel, bidx + r);
                qA = fmaf(vA, mks, qA);
                qB = fmaf(vB, mks, qB);
            }
        }
        sm.pbuf[w * 64 + lane]      = qA;
        sm.pbuf[w * 64 + lane + 32] = qB;
    }
    __syncthreads();  // S1

    // ---- warp-0 chain: qin -> q -> a_h (fp16 [h][j]) ----
    if (w == 0) {
        float d = 0.f;
#pragma unroll
        for (int i = 0; i < 8; i++) d += sm.red[i];
        float inv = 1.0f / fmaxf(d, 1.0f);
        float q0 = 0.f, q1 = 0.f;
#pragma unroll
        for (int i = 0; i < 8; i++) {
            q0 += sm.pbuf[i * 64 + lane];
            q1 += sm.pbuf[i * 64 + lane + 32];
        }
        sm.qin[lane] = q0 * inv;
        sm.qin[lane + 32] = q1 * inv;
        __syncwarp();
        float a0 = 0.f, a1 = 0.f;
#pragma unroll
        for (int j = 0; j < 64; j++) {
            float qj = sm.qin[j];
            a0 = fmaf(qj, __ldg(&wq[j * 64 + lane]), a0);
            a1 = fmaf(qj, __ldg(&wq[j * 64 + lane + 32]), a1);
        }
        sm.qsm[lane] = a0;
        sm.qsm[lane + 32] = a1;
        __syncwarp();
#pragma unroll 1
        for (int t = 0; t < 16; t++) {
            int idx = t * 32 + lane;
            int j = idx >> 3, h = idx & 7;
            float acc = 0.f;
#pragma unroll
            for (int c = 0; c < 8; c++)
                acc = fmaf(sm.qsm[h * 8 + c], __ldg(&wk[j * 64 + h * 8 + c]), acc);
            sm.a_h[h * XP + j] = __float2half(acc * 0.35355339059327373f);  // 1/sqrt(C)
        }
    }
    __syncthreads();  // S2

    // ---- Logits via HMMA: warp w rows w*64..+63 ----
    {
        uint32_t Bf[8];
        ldmA(Bf,     s2u(&sm.a_h[bRowSel * XP + bKSel]));
        ldmA(Bf + 4, s2u(&sm.a_h[bRowSel * XP + 32 + bKSel]));
#pragma unroll
        for (int mt = 0; mt < 4; mt++) {
            int s0 = w * 64 + mt * 16;
            uint32_t A[4][4];
#pragma unroll
            for (int kt = 0; kt < 4; kt++)
                ldmA(A[kt], s2u(&sm.x[(s0 + (lane & 15)) * XP + kt * 16 + ((lane >> 4) << 3)]));
            float acc[4] = {0, 0, 0, 0};
#pragma unroll
            for (int kt = 0; kt < 4; kt++) mma16816(acc, A[kt], &Bf[kt * 2]);
            int r = s0 + (lane >> 2);
            int h0 = (lane & 3) * 2;
            float mA = sm.maskS[r], mB = sm.maskS[r + 8];
            sm.u.LG[h0 * 512 + r]           = (mA != 0.0f) ? acc[0] : -1e9f;
            sm.u.LG[(h0 + 1) * 512 + r]     = (mA != 0.0f) ? acc[1] : -1e9f;
            sm.u.LG[h0 * 512 + r + 8]       = (mB != 0.0f) ? acc[2] : -1e9f;
            sm.u.LG[(h0 + 1) * 512 + r + 8] = (mB != 0.0f) ? acc[3] : -1e9f;
        }
    }
    __syncthreads();  // S3

    // ---- softmax, warp w owns head w ----
    {
        float vals[16];
        float lm = -3.4e38f;
#pragma unroll
        for (int k = 0; k < 16; k++) {
            vals[k] = sm.u.LG[w * 512 + lane + k * 32];
            lm = fmaxf(lm, vals[k]);
        }
#pragma unroll
        for (int o = 16; o; o >>= 1) lm = fmaxf(lm, __shfl_xor_sync(0xffffffffu, lm, o));
        float ls = 0.f;
#pragma unroll
        for (int k = 0; k < 16; k++) {
            vals[k] = __expf(vals[k] - lm);
            ls += vals[k];
        }
#pragma unroll
        for (int o = 16; o; o >>= 1) ls += __shfl_xor_sync(0xffffffffu, ls, o);
        float inv = 1.0f / ls;
#pragma unroll
        for (int k = 0; k < 16; k++) sm.u.LG[w * 512 + lane + k * 32] = vals[k] * inv;
    }
    __syncthreads();  // S4: attn ready

    // ---- Fused Pass V + og: warp w rows w*64..+63, all 64 cols ----
    {
        float ogp[16];
#pragma unroll
        for (int k = 0; k < 16; k++) ogp[k] = 0.f;
        const int k0 = (lane & 3) * 2;
#pragma unroll 1
        for (int mt = 0; mt < 4; mt++) {
            int s0 = w * 64 + mt * 16;
            uint32_t A[4][4];
#pragma unroll
            for (int kt = 0; kt < 4; kt++)
                ldmA(A[kt], s2u(&sm.x[(s0 + (lane & 15)) * XP + kt * 16 + ((lane >> 4) << 3)]));
            int r = s0 + (lane >> 2);
#pragma unroll
            for (int nt = 0; nt < 8; nt++) {
                uint32_t Bv[8];
                ldmA(Bv,     s2u(&sm.wvB[(nt * 8 + bRowSel) * XP + bKSel]));
                ldmA(Bv + 4, s2u(&sm.wvB[(nt * 8 + bRowSel) * XP + 32 + bKSel]));
                float acc[4] = {0, 0, 0, 0};
#pragma unroll
                for (int kt = 0; kt < 4; kt++) mma16816(acc, A[kt], &Bv[kt * 2]);
                float aA = sm.u.LG[nt * 512 + r];
                float aB = sm.u.LG[nt * 512 + r + 8];
                ogp[2 * nt]     = fmaf(aA, acc[0], fmaf(aB, acc[2], ogp[2 * nt]));
                ogp[2 * nt + 1] = fmaf(aA, acc[1], fmaf(aB, acc[3], ogp[2 * nt + 1]));
            }
        }
#pragma unroll
        for (int k = 0; k < 16; k++) {
            ogp[k] += __shfl_xor_sync(0xffffffffu, ogp[k], 4);
            ogp[k] += __shfl_xor_sync(0xffffffffu, ogp[k], 8);
            ogp[k] += __shfl_xor_sync(0xffffffffu, ogp[k], 16);
        }
        if (lane < 4) {
#pragma unroll
            for (int nt = 0; nt < 8; nt++) {
                sm.pbuf[w * 64 + nt * 8 + k0]     = ogp[2 * nt];
                sm.pbuf[w * 64 + nt * 8 + k0 + 1] = ogp[2 * nt + 1];
            }
        }
    }
    __syncthreads();  // S5: LG dead from here; og partials ready

    // ---- og reduce + stage wg/wo tiles into the union ----
    if (tid < 64) {
        float acc = 0.f;
#pragma unroll
        for (int w2 = 0; w2 < 8; w2++) acc += sm.pbuf[w2 * 64 + tid];
        sm.og[tid] = acc;
    }
    for (int idx = tid; idx < 4096; idx += NT) {
        int n = idx & 63, k = idx >> 6;
        sm.u.go.wgB[n * XP + k] = __float2half(__ldg(&wg[k * 64 + n]));
        sm.u.go.woB[n * XP + k] = __float2half(__ldg(&wo[k * 64 + n]));
    }
    __syncthreads();  // S6: og + wg/wo tiles ready

    // ---- Fused G+O: warp w rows w*64..+63 (transient per-nt D-frags) ----
    {
        const int k0 = (lane & 3) * 2;
#pragma unroll 1
        for (int mt2 = 0; mt2 < 4; mt2++) {
            int s0 = w * 64 + mt2 * 16;
            uint32_t Ax[4][4];
#pragma unroll
            for (int kt = 0; kt < 4; kt++)
                ldmA(Ax[kt], s2u(&sm.x[(s0 + (lane & 15)) * XP + kt * 16 + ((lane >> 4) << 3)]));
            // GEMM1 + epilogue per nt: acc transient, pack straight into Ap
            uint32_t Ap[4][4];
#pragma unroll
            for (int nt = 0; nt < 8; nt++) {
                uint32_t Bg[8];
                ldmA(Bg,     s2u(&sm.u.go.wgB[(nt * 8 + bRowSel) * XP + bKSel]));
                ldmA(Bg + 4, s2u(&sm.u.go.wgB[(nt * 8 + bRowSel) * XP + 32 + bKSel]));
                float acc[4] = {0, 0, 0, 0};
#pragma unroll
                for (int kt = 0; kt < 4; kt++) mma16816(acc, Ax[kt], &Bg[kt * 2]);
                int c = nt * 8 + k0;
                float ogv0 = sm.og[c], ogv1 = sm.og[c + 1];
                float bg0 = sm.bgS[c], bg1 = sm.bgS[c + 1];
                float t0 = ogv0 * sgm(acc[0] + bg0);
                float t1 = ogv1 * sgm(acc[1] + bg1);
                float t2 = ogv0 * sgm(acc[2] + bg0);
                float t3 = ogv1 * sgm(acc[3] + bg1);
                int kt2 = nt >> 1, hi = nt & 1;
                Ap[kt2][hi * 2]     = packh2(t0, t1);
                Ap[kt2][hi * 2 + 1] = packh2(t2, t3);
            }
            // GEMM2: out = (t @ wo + bo) * mask -> global
            int r = s0 + (lane >> 2);
            float mA = sm.maskS[r], mB = sm.maskS[r + 8];
#pragma unroll
            for (int nt2 = 0; nt2 < 8; nt2++) {
                uint32_t Bo[8];
                ldmA(Bo,     s2u(&sm.u.go.woB[(nt2 * 8 + bRowSel) * XP + bKSel]));
                ldmA(Bo + 4, s2u(&sm.u.go.woB[(nt2 * 8 + bRowSel) * XP + 32 + bKSel]));
                float acc2[4] = {0, 0, 0, 0};
#pragma unroll
                for (int kt = 0; kt < 4; kt++) mma16816(acc2, Ap[kt], &Bo[kt * 2]);
                int c = nt2 * 8 + k0;
                float bo0 = __ldg(&bo[c]), bo1 = __ldg(&bo[c + 1]);
                *reinterpret_cast<float2*>(oBase + (size_t)r * rowStride + c) =
                    make_float2((acc2[0] + bo0) * mA, (acc2[1] + bo1) * mA);
                *reinterpret_cast<float2*>(oBase + (size_t)(r + 8) * rowStride + c) =
                    make_float2((acc2[2] + bo0) * mB, (acc2[3] + bo1) * mB);
            }
        }
    }
}

extern "C" void kernel_launch(void* const* d_in, const int* in_sizes, int n_in,
                              void* d_out, int out_size)
{
    (void)in_sizes; (void)n_in; (void)out_size;
    const float* m    = (const float*)d_in[0];
    const float* mask = (const float*)d_in[1];
    const float* lnw  = (const float*)d_in[2];
    const float* lnb  = (const float*)d_in[3];
    const float* wq   = (const float*)d_in[4];
    const float* wk   = (const float*)d_in[5];
    const float* wv   = (const float*)d_in[6];
    const float* wg   = (const float*)d_in[7];
    const float* bg   = (const float*)d_in[8];
    const float* wo   = (const float*)d_in[9];
    const float* bo   = (const float*)d_in[10];
    float* out = (float*)d_out;

    cudaFuncSetAttribute(msa_col_global_attn,
                         cudaFuncAttributeMaxDynamicSharedMemorySize,
                         (int)sizeof(SMem));
    msa_col_global_attn<<<Bb * Ll, NT, sizeof(SMem)>>>(
        m, mask, lnw, lnb, wq, wk, wv, wg, bg, wo, bo, out);
}

// round 17
// speedup vs baseline: 1.2451x; 1.1029x over previous
#include <cuda_runtime.h>
#include <cuda_fp16.h>
#include <cstdint>
#include <cstddef>

#define NT 256
#define XP 72   // halves per smem matrix row (144B: conflict-free ldmatrix, 16B-aligned)

namespace {
constexpr int Bb = 2, Ss = 512, Ll = 384, CMc = 64;

struct __align__(16) SMem {
    __half x[512 * XP];      // post-LN x fp16, row-major [s][c]     73,728B
    __half wvB[64 * XP];     // wv^T tile: row n, col k               9,216B
    union {
        float LG[8 * 512];   // logits->attn [h][s]                  16,384B
        struct { __half wgB[64 * XP]; __half woB[64 * XP]; } go;  // 18,432B
    } u;
    float maskS[512];
    float pbuf[8 * 64];      // qin partials; og partials
    __half a_h[8 * XP];      // a fp16 [h][j]
    float qin[64];
    float qsm[64];
    float og[64];
    float bgS[64];
    float red[8];
};
}  // namespace

__device__ __forceinline__ uint32_t s2u(const void* p) {
    uint32_t a;
    asm("{ .reg .u64 t; cvta.to.shared.u64 t, %1; cvt.u32.u64 %0, t; }" : "=r"(a) : "l"(p));
    return a;
}
__device__ __forceinline__ void ldmA(uint32_t* a, uint32_t addr) {
    asm volatile("ldmatrix.sync.aligned.m8n8.x4.shared.b16 {%0,%1,%2,%3}, [%4];"
                 : "=r"(a[0]), "=r"(a[1]), "=r"(a[2]), "=r"(a[3]) : "r"(addr));
}
__device__ __forceinline__ void mma16816(float* d, const uint32_t* a, const uint32_t* b) {
    asm volatile(
        "mma.sync.aligned.m16n8k16.row.col.f32.f16.f16.f32 "
        "{%0,%1,%2,%3}, {%4,%5,%6,%7}, {%8,%9}, {%0,%1,%2,%3};"
        : "+f"(d[0]), "+f"(d[1]), "+f"(d[2]), "+f"(d[3])
        : "r"(a[0]), "r"(a[1]), "r"(a[2]), "r"(a[3]), "r"(b[0]), "r"(b[1]));
}
__device__ __forceinline__ float sgm(float x) { return 1.0f / (1.0f + __expf(-x)); }
__device__ __forceinline__ uint32_t packh2(float a, float b) {
    __half2 h = __floats2half2_rn(a, b);
    return *reinterpret_cast<uint32_t*>(&h);
}

__global__ void __launch_bounds__(NT, 2)
msa_col_global_attn(const float* __restrict__ m, const float* __restrict__ msa_mask,
                    const float* __restrict__ lnw, const float* __restrict__ lnb,
                    const float* __restrict__ wq, const float* __restrict__ wk,
                    const float* __restrict__ wv, const float* __restrict__ wg,
                    const float* __restrict__ bg, const float* __restrict__ wo,
                    const float* __restrict__ bo, float* __restrict__ out)
{
    extern __shared__ __align__(16) char smraw[];
    SMem& sm = *reinterpret_cast<SMem*>(smraw);
    const int tid = threadIdx.x;
    const int w = tid >> 5, lane = tid & 31;
    const int b = blockIdx.x / Ll, l = blockIdx.x - b * Ll;
    const size_t rowStride = (size_t)Ll * CMc;
    const float* mBase = m + ((size_t)b * Ss * Ll + l) * CMc;
    float* oBase = out + ((size_t)b * Ss * Ll + l) * CMc;

    // ---- Phase 0: mask + wv tile + bg ----
    const int row0 = w * 64 + lane, row1 = row0 + 32;
    {
        float mkA = msa_mask[((size_t)b * Ss + row0) * Ll + l];
        float mkB = msa_mask[((size_t)b * Ss + row1) * Ll + l];
        sm.maskS[row0] = mkA;
        sm.maskS[row1] = mkB;
        float ms = mkA + mkB;
#pragma unroll
        for (int o = 16; o; o >>= 1) ms += __shfl_xor_sync(0xffffffffu, ms, o);
        if (lane == 0) sm.red[w] = ms;
    }
    for (int idx = tid; idx < 1024; idx += NT) {
        int n4 = (idx & 15) * 4, k = idx >> 4;
        float4 v = __ldg(reinterpret_cast<const float4*>(&wv[k * 64 + n4]));
        sm.wvB[(n4 + 0) * XP + k] = __float2half(v.x);
        sm.wvB[(n4 + 1) * XP + k] = __float2half(v.y);
        sm.wvB[(n4 + 2) * XP + k] = __float2half(v.z);
        sm.wvB[(n4 + 3) * XP + k] = __float2half(v.w);
    }
    if (tid < 64) sm.bgS[tid] = __ldg(&bg[tid]);
    __syncwarp();

    // ---- LayerNorm: 4 threads per row, 16 cols/thread; fold masked column-sum ----
    {
        const int ci = (lane & 3) * 16;   // col base
        const int rsub = lane >> 2;       // row within 8-row pass
        float4 lw0 = *reinterpret_cast<const float4*>(&lnw[ci]);
        float4 lw1 = *reinterpret_cast<const float4*>(&lnw[ci + 4]);
        float4 lw2 = *reinterpret_cast<const float4*>(&lnw[ci + 8]);
        float4 lw3 = *reinterpret_cast<const float4*>(&lnw[ci + 12]);
        float4 lb0 = *reinterpret_cast<const float4*>(&lnb[ci]);
        float4 lb1 = *reinterpret_cast<const float4*>(&lnb[ci + 4]);
        float4 lb2 = *reinterpret_cast<const float4*>(&lnb[ci + 8]);
        float4 lb3 = *reinterpret_cast<const float4*>(&lnb[ci + 12]);
        float qac[16];
#pragma unroll
        for (int i = 0; i < 16; i++) qac[i] = 0.f;
#pragma unroll 1
        for (int ps = 0; ps < 8; ps++) {
            int s = w * 64 + ps * 8 + rsub;
            const float* mp = mBase + (size_t)s * rowStride + ci;
            float4 v0 = __ldg(reinterpret_cast<const float4*>(mp));
            float4 v1 = __ldg(reinterpret_cast<const float4*>(mp + 4));
            float4 v2 = __ldg(reinterpret_cast<const float4*>(mp + 8));
            float4 v3 = __ldg(reinterpret_cast<const float4*>(mp + 12));
            float su = ((v0.x + v0.y) + (v0.z + v0.w)) + ((v1.x + v1.y) + (v1.z + v1.w)) +
                       ((v2.x + v2.y) + (v2.z + v2.w)) + ((v3.x + v3.y) + (v3.z + v3.w));
            float sq = v0.x * v0.x;
            sq = fmaf(v0.y, v0.y, sq); sq = fmaf(v0.z, v0.z, sq); sq = fmaf(v0.w, v0.w, sq);
            sq = fmaf(v1.x, v1.x, sq); sq = fmaf(v1.y, v1.y, sq);
            sq = fmaf(v1.z, v1.z, sq); sq = fmaf(v1.w, v1.w, sq);
            sq = fmaf(v2.x, v2.x, sq); sq = fmaf(v2.y, v2.y, sq);
            sq = fmaf(v2.z, v2.z, sq); sq = fmaf(v2.w, v2.w, sq);
            sq = fmaf(v3.x, v3.x, sq); sq = fmaf(v3.y, v3.y, sq);
            sq = fmaf(v3.z, v3.z, sq); sq = fmaf(v3.w, v3.w, sq);
#pragma unroll
            for (int o = 1; o < 4; o <<= 1) {
                su += __shfl_xor_sync(0xffffffffu, su, o);
                sq += __shfl_xor_sync(0xffffffffu, sq, o);
            }
            float mu = su * (1.0f / 64.0f);
            float var = sq * (1.0f / 64.0f) - mu * mu;
            float rs = rsqrtf(var + 1e-5f);
            float t[16];
            t[0]  = (v0.x - mu) * rs * lw0.x + lb0.x;
            t[1]  = (v0.y - mu) * rs * lw0.y + lb0.y;
            t[2]  = (v0.z - mu) * rs * lw0.z + lb0.z;
            t[3]  = (v0.w - mu) * rs * lw0.w + lb0.w;
            t[4]  = (v1.x - mu) * rs * lw1.x + lb1.x;
            t[5]  = (v1.y - mu) * rs * lw1.y + lb1.y;
            t[6]  = (v1.z - mu) * rs * lw1.z + lb1.z;
            t[7]  = (v1.w - mu) * rs * lw1.w + lb1.w;
            t[8]  = (v2.x - mu) * rs * lw2.x + lb2.x;
            t[9]  = (v2.y - mu) * rs * lw2.y + lb2.y;
            t[10] = (v2.z - mu) * rs * lw2.z + lb2.z;
            t[11] = (v2.w - mu) * rs * lw2.w + lb2.w;
            t[12] = (v3.x - mu) * rs * lw3.x + lb3.x;
            t[13] = (v3.y - mu) * rs * lw3.y + lb3.y;
            t[14] = (v3.z - mu) * rs * lw3.z + lb3.z;
            t[15] = (v3.w - mu) * rs * lw3.w + lb3.w;
            uint4 p0, p1;
            p0.x = packh2(t[0], t[1]);   p0.y = packh2(t[2], t[3]);
            p0.z = packh2(t[4], t[5]);   p0.w = packh2(t[6], t[7]);
            p1.x = packh2(t[8], t[9]);   p1.y = packh2(t[10], t[11]);
            p1.z = packh2(t[12], t[13]); p1.w = packh2(t[14], t[15]);
            *reinterpret_cast<uint4*>(&sm.x[s * XP + ci])     = p0;
            *reinterpret_cast<uint4*>(&sm.x[s * XP + ci + 8]) = p1;
            float mks = sm.maskS[s];
#pragma unroll
            for (int i = 0; i < 16; i++) qac[i] = fmaf(t[i], mks, qac[i]);
        }
#pragma unroll
        for (int i = 0; i < 16; i++) {
            qac[i] += __shfl_xor_sync(0xffffffffu, qac[i], 4);
            qac[i] += __shfl_xor_sync(0xffffffffu, qac[i], 8);
            qac[i] += __shfl_xor_sync(0xffffffffu, qac[i], 16);
        }
        if (lane < 4) {
            *reinterpret_cast<float4*>(&sm.pbuf[w * 64 + ci]) =
                make_float4(qac[0], qac[1], qac[2], qac[3]);
            *reinterpret_cast<float4*>(&sm.pbuf[w * 64 + ci + 4]) =
                make_float4(qac[4], qac[5], qac[6], qac[7]);
            *reinterpret_cast<float4*>(&sm.pbuf[w * 64 + ci + 8]) =
                make_float4(qac[8], qac[9], qac[10], qac[11]);
            *reinterpret_cast<float4*>(&sm.pbuf[w * 64 + ci + 12]) =
                make_float4(qac[12], qac[13], qac[14], qac[15]);
        }
    }
    __syncthreads();  // S1

    // ---- warp-0 chain: qin -> q -> a_h (fp16 [h][j]) ----
    if (w == 0) {
        float d = 0.f;
#pragma unroll
        for (int i = 0; i < 8; i++) d += sm.red[i];
        float inv = 1.0f / fmaxf(d, 1.0f);
        float q0 = 0.f, q1 = 0.f;
#pragma unroll
        for (int i = 0; i < 8; i++) {
            q0 += sm.pbuf[i * 64 + lane];
            q1 += sm.pbuf[i * 64 + lane + 32];
        }
        sm.qin[lane] = q0 * inv;
        sm.qin[lane + 32] = q1 * inv;
        __syncwarp();
        float a0 = 0.f, a1 = 0.f;
#pragma unroll
        for (int j = 0; j < 64; j++) {
            float qj = sm.qin[j];
            a0 = fmaf(qj, __ldg(&wq[j * 64 + lane]), a0);
            a1 = fmaf(qj, __ldg(&wq[j * 64 + lane + 32]), a1);
        }
        sm.qsm[lane] = a0;
        sm.qsm[lane + 32] = a1;
        __syncwarp();
#pragma unroll 1
        for (int t = 0; t < 16; t++) {
            int idx = t * 32 + lane;
            int j = idx >> 3, h = idx & 7;
            float acc = 0.f;
#pragma unroll
            for (int c = 0; c < 8; c++)
                acc = fmaf(sm.qsm[h * 8 + c], __ldg(&wk[j * 64 + h * 8 + c]), acc);
            sm.a_h[h * XP + j] = __float2half(acc * 0.35355339059327373f);  // 1/sqrt(C)
        }
    }
    __syncthreads();  // S2

    // ---- Logits via HMMA: warp w rows w*64..+63 ----
    {
        uint32_t Bf[4][2];
#pragma unroll
        for (int kt = 0; kt < 4; kt++) {
            int row = lane >> 2;
            int col = kt * 16 + (lane & 3) * 2;
            Bf[kt][0] = *reinterpret_cast<const uint32_t*>(&sm.a_h[row * XP + col]);
            Bf[kt][1] = *reinterpret_cast<const uint32_t*>(&sm.a_h[row * XP + col + 8]);
        }
#pragma unroll
        for (int mt = 0; mt < 4; mt++) {
            int s0 = w * 64 + mt * 16;
            uint32_t A[4][4];
#pragma unroll
            for (int kt = 0; kt < 4; kt++)
                ldmA(A[kt], s2u(&sm.x[(s0 + (lane & 15)) * XP + kt * 16 + ((lane >> 4) << 3)]));
            float acc[4] = {0, 0, 0, 0};
#pragma unroll
            for (int kt = 0; kt < 4; kt++) mma16816(acc, A[kt], Bf[kt]);
            int r = s0 + (lane >> 2);
            int h0 = (lane & 3) * 2;
            float mA = sm.maskS[r], mB = sm.maskS[r + 8];
            sm.u.LG[h0 * 512 + r]           = (mA != 0.0f) ? acc[0] : -1e9f;
            sm.u.LG[(h0 + 1) * 512 + r]     = (mA != 0.0f) ? acc[1] : -1e9f;
            sm.u.LG[h0 * 512 + r + 8]       = (mB != 0.0f) ? acc[2] : -1e9f;
            sm.u.LG[(h0 + 1) * 512 + r + 8] = (mB != 0.0f) ? acc[3] : -1e9f;
        }
    }
    __syncthreads();  // S3

    // ---- softmax, warp w owns head w ----
    {
        float vals[16];
        float lm = -3.4e38f;
#pragma unroll
        for (int k = 0; k < 16; k++) {
            vals[k] = sm.u.LG[w * 512 + lane + k * 32];
            lm = fmaxf(lm, vals[k]);
        }
#pragma unroll
        for (int o = 16; o; o >>= 1) lm = fmaxf(lm, __shfl_xor_sync(0xffffffffu, lm, o));
        float ls = 0.f;
#pragma unroll
        for (int k = 0; k < 16; k++) {
            vals[k] = __expf(vals[k] - lm);
            ls += vals[k];
        }
#pragma unroll
        for (int o = 16; o; o >>= 1) ls += __shfl_xor_sync(0xffffffffu, ls, o);
        float inv = 1.0f / ls;
#pragma unroll
        for (int k = 0; k < 16; k++) sm.u.LG[w * 512 + lane + k * 32] = vals[k] * inv;
    }
    __syncthreads();  // S4: attn ready

    // ---- Fused Pass V + og: warp w rows w*64..+63, all 64 cols ----
    {
        float ogp[16];
#pragma unroll
        for (int k = 0; k < 16; k++) ogp[k] = 0.f;
        const int k0 = (lane & 3) * 2;
#pragma unroll 1
        for (int mt = 0; mt < 4; mt++) {
            int s0 = w * 64 + mt * 16;
            uint32_t A[4][4];
#pragma unroll
            for (int kt = 0; kt < 4; kt++)
                ldmA(A[kt], s2u(&sm.x[(s0 + (lane & 15)) * XP + kt * 16 + ((lane >> 4) << 3)]));
            int r = s0 + (lane >> 2);
#pragma unroll
            for (int nt = 0; nt < 8; nt++) {
                uint32_t Bv[4][2];
#pragma unroll
                for (int kt = 0; kt < 4; kt++) {
                    int row = nt * 8 + (lane >> 2);
                    int col = kt * 16 + k0;
                    Bv[kt][0] = *reinterpret_cast<const uint32_t*>(&sm.wvB[row * XP + col]);
                    Bv[kt][1] = *reinterpret_cast<const uint32_t*>(&sm.wvB[row * XP + col + 8]);
                }
                float acc[4] = {0, 0, 0, 0};
#pragma unroll
                for (int kt = 0; kt < 4; kt++) mma16816(acc, A[kt], Bv[kt]);
                float aA = sm.u.LG[nt * 512 + r];
                float aB = sm.u.LG[nt * 512 + r + 8];
                ogp[2 * nt]     = fmaf(aA, acc[0], fmaf(aB, acc[2], ogp[2 * nt]));
                ogp[2 * nt + 1] = fmaf(aA, acc[1], fmaf(aB, acc[3], ogp[2 * nt + 1]));
            }
        }
#pragma unroll
        for (int k = 0; k < 16; k++) {
            ogp[k] += __shfl_xor_sync(0xffffffffu, ogp[k], 4);
            ogp[k] += __shfl_xor_sync(0xffffffffu, ogp[k], 8);
            ogp[k] += __shfl_xor_sync(0xffffffffu, ogp[k], 16);
        }
        if (lane < 4) {
#pragma unroll
            for (int nt = 0; nt < 8; nt++) {
                sm.pbuf[w * 64 + nt * 8 + k0]     = ogp[2 * nt];
                sm.pbuf[w * 64 + nt * 8 + k0 + 1] = ogp[2 * nt + 1];
            }
        }
    }
    __syncthreads();  // S5: LG dead from here; og partials ready

    // ---- og reduce + stage wg/wo tiles into the union ----
    if (tid < 64) {
        float acc = 0.f;
#pragma unroll
        for (int w2 = 0; w2 < 8; w2++) acc += sm.pbuf[w2 * 64 + tid];
        sm.og[tid] = acc;
    }
    for (int idx = tid; idx < 1024; idx += NT) {
        int n4 = (idx & 15) * 4, k = idx >> 4;
        float4 g = __ldg(reinterpret_cast<const float4*>(&wg[k * 64 + n4]));
        sm.u.go.wgB[(n4 + 0) * XP + k] = __float2half(g.x);
        sm.u.go.wgB[(n4 + 1) * XP + k] = __float2half(g.y);
        sm.u.go.wgB[(n4 + 2) * XP + k] = __float2half(g.z);
        sm.u.go.wgB[(n4 + 3) * XP + k] = __float2half(g.w);
        float4 o2 = __ldg(reinterpret_cast<const float4*>(&wo[k * 64 + n4]));
        sm.u.go.woB[(n4 + 0) * XP + k] = __float2half(o2.x);
        sm.u.go.woB[(n4 + 1) * XP + k] = __float2half(o2.y);
        sm.u.go.woB[(n4 + 2) * XP + k] = __float2half(o2.z);
        sm.u.go.woB[(n4 + 3) * XP + k] = __float2half(o2.w);
    }
    __syncthreads();  // S6: og + wg/wo tiles ready

    // ---- Fused G+O: warp w rows w*64..+63 (transient per-nt D-frags) ----
    {
        const int k0 = (lane & 3) * 2;
#pragma unroll 1
        for (int mt2 = 0; mt2 < 4; mt2++) {
            int s0 = w * 64 + mt2 * 16;
            uint32_t Ax[4][4];
#pragma unroll
            for (int kt = 0; kt < 4; kt++)
                ldmA(Ax[kt], s2u(&sm.x[(s0 + (lane & 15)) * XP + kt * 16 + ((lane >> 4) << 3)]));
            uint32_t Ap[4][4];
#pragma unroll
            for (int nt = 0; nt < 8; nt++) {
                uint32_t Bg[4][2];
#pragma unroll
                for (int kt = 0; kt < 4; kt++) {
                    int row = nt * 8 + (lane >> 2);
                    int col = kt * 16 + k0;
                    Bg[kt][0] = *reinterpret_cast<const uint32_t*>(&sm.u.go.wgB[row * XP + col]);
                    Bg[kt][1] = *reinterpret_cast<const uint32_t*>(&sm.u.go.wgB[row * XP + col + 8]);
                }
                float acc[4] = {0, 0, 0, 0};
#pragma unroll
                for (int kt = 0; kt < 4; kt++) mma16816(acc, Ax[kt], Bg[kt]);
                int c = nt * 8 + k0;
                float ogv0 = sm.og[c], ogv1 = sm.og[c + 1];
                float bg0 = sm.bgS[c], bg1 = sm.bgS[c + 1];
                float t0 = ogv0 * sgm(acc[0] + bg0);
                float t1 = ogv1 * sgm(acc[1] + bg1);
                float t2 = ogv0 * sgm(acc[2] + bg0);
                float t3 = ogv1 * sgm(acc[3] + bg1);
                int kt2 = nt >> 1, hi = nt & 1;
                Ap[kt2][hi * 2]     = packh2(t0, t1);
                Ap[kt2][hi * 2 + 1] = packh2(t2, t3);
            }
            int r = s0 + (lane >> 2);
            float mA = sm.maskS[r], mB = sm.maskS[r + 8];
#pragma unroll
            for (int nt2 = 0; nt2 < 8; nt2++) {
                uint32_t Bo[4][2];
#pragma unroll
                for (int kt = 0; kt < 4; kt++) {
                    int row = nt2 * 8 + (lane >> 2);
                    int col = kt * 16 + k0;
                    Bo[kt][0] = *reinterpret_cast<const uint32_t*>(&sm.u.go.woB[row * XP + col]);
                    Bo[kt][1] = *reinterpret_cast<const uint32_t*>(&sm.u.go.woB[row * XP + col + 8]);
                }
                float acc2[4] = {0, 0, 0, 0};
#pragma unroll
                for (int kt = 0; kt < 4; kt++) mma16816(acc2, Ap[kt], Bo[kt]);
                int c = nt2 * 8 + k0;
                float bo0 = __ldg(&bo[c]), bo1 = __ldg(&bo[c + 1]);
                *reinterpret_cast<float2*>(oBase + (size_t)r * rowStride + c) =
                    make_float2((acc2[0] + bo0) * mA, (acc2[1] + bo1) * mA);
                *reinterpret_cast<float2*>(oBase + (size_t)(r + 8) * rowStride + c) =
                    make_float2((acc2[2] + bo0) * mB, (acc2[3] + bo1) * mB);
            }
        }
    }
}

extern "C" void kernel_launch(void* const* d_in, const int* in_sizes, int n_in,
                              void* d_out, int out_size)
{
    (void)in_sizes; (void)n_in; (void)out_size;
    const float* m    = (const float*)d_in[0];
    const float* mask = (const float*)d_in[1];
    const float* lnw  = (const float*)d_in[2];
    const float* lnb  = (const float*)d_in[3];
    const float* wq   = (const float*)d_in[4];
    const float* wk   = (const float*)d_in[5];
    const float* wv   = (const float*)d_in[6];
    const float* wg   = (const float*)d_in[7];
    const float* bg   = (const float*)d_in[8];
    const float* wo   = (const float*)d_in[9];
    const float* bo   = (const float*)d_in[10];
    float* out = (float*)d_out;

    cudaFuncSetAttribute(msa_col_global_attn,
                         cudaFuncAttributeMaxDynamicSharedMemorySize,
                         (int)sizeof(SMem));
    msa_col_global_attn<<<Bb * Ll, NT, sizeof(SMem)>>>(
        m, mask, lnw, lnb, wq, wk, wv, wg, bg, wo, bo, out);
}